// round 1
// baseline (speedup 1.0000x reference)
#include <cuda_runtime.h>
#include <cuda_bf16.h>
#include <cstdint>

// Problem constants
#define BATCH   2
#define SEQ     2048
#define EMB     1024
#define HEADS   16
#define HDIM    64
#define QKV_N   3072          // 3*EMB
#define M_ROWS  (BATCH*SEQ)   // 4096

// Scratch (allocation-free rule: __device__ globals)
__device__ float g_qkv[(size_t)BATCH * SEQ * QKV_N];   // 48 MB
__device__ float g_ctx[(size_t)BATCH * SEQ * EMB];     // 16 MB

// ---------------------------------------------------------------------------
// NT GEMM: C[M,N] = A[M,K] @ B[N,K]^T + bias[N]
// Both A and B are K-major (row-major with K contiguous). 128x128x16 tiles,
// 256 threads, 8x8 per-thread microtile.
// Requires M%128==0, N%128==0, K%16==0 (true for all our shapes).
// ---------------------------------------------------------------------------
__global__ __launch_bounds__(256) void gemm_nt_kernel(
    const float* __restrict__ A, const float* __restrict__ B,
    const float* __restrict__ bias, float* __restrict__ C,
    int M, int N, int K)
{
    __shared__ float As[16][132];   // [k][m], padded
    __shared__ float Bs[16][132];   // [k][n], padded

    const int tid = threadIdx.x;
    const int bm  = blockIdx.y * 128;
    const int bn  = blockIdx.x * 128;
    const int ty  = tid >> 4;          // 0..15 -> 8 rows each
    const int tx  = tid & 15;          // 0..15 -> 8 cols each
    const int lr  = tid >> 1;          // 0..127 load row
    const int lc  = (tid & 1) << 3;    // 0 or 8

    const float* Ap = A + (size_t)(bm + lr) * K + lc;
    const float* Bp = B + (size_t)(bn + lr) * K + lc;

    float acc[8][8];
#pragma unroll
    for (int i = 0; i < 8; i++)
#pragma unroll
        for (int j = 0; j < 8; j++) acc[i][j] = 0.f;

    for (int k0 = 0; k0 < K; k0 += 16) {
        float4 a0 = *(const float4*)(Ap + k0);
        float4 a1 = *(const float4*)(Ap + k0 + 4);
        float4 b0 = *(const float4*)(Bp + k0);
        float4 b1 = *(const float4*)(Bp + k0 + 4);

        __syncthreads();   // previous tile fully consumed
        As[lc+0][lr] = a0.x; As[lc+1][lr] = a0.y; As[lc+2][lr] = a0.z; As[lc+3][lr] = a0.w;
        As[lc+4][lr] = a1.x; As[lc+5][lr] = a1.y; As[lc+6][lr] = a1.z; As[lc+7][lr] = a1.w;
        Bs[lc+0][lr] = b0.x; Bs[lc+1][lr] = b0.y; Bs[lc+2][lr] = b0.z; Bs[lc+3][lr] = b0.w;
        Bs[lc+4][lr] = b1.x; Bs[lc+5][lr] = b1.y; Bs[lc+6][lr] = b1.z; Bs[lc+7][lr] = b1.w;
        __syncthreads();

#pragma unroll
        for (int kk = 0; kk < 16; kk++) {
            float ar[8], br[8];
            *(float4*)&ar[0] = *(float4*)&As[kk][ty*8];
            *(float4*)&ar[4] = *(float4*)&As[kk][ty*8 + 4];
            *(float4*)&br[0] = *(float4*)&Bs[kk][tx*8];
            *(float4*)&br[4] = *(float4*)&Bs[kk][tx*8 + 4];
#pragma unroll
            for (int i = 0; i < 8; i++)
#pragma unroll
                for (int j = 0; j < 8; j++)
                    acc[i][j] += ar[i] * br[j];
        }
    }

#pragma unroll
    for (int i = 0; i < 8; i++) {
        const size_t row = (size_t)(bm + ty*8 + i);
#pragma unroll
        for (int j = 0; j < 8; j += 4) {
            const int col = bn + tx*8 + j;
            float4 o;
            o.x = acc[i][j+0] + bias[col+0];
            o.y = acc[i][j+1] + bias[col+1];
            o.z = acc[i][j+2] + bias[col+2];
            o.w = acc[i][j+3] + bias[col+3];
            *(float4*)&C[row * N + col] = o;
        }
    }
}

// ---------------------------------------------------------------------------
// Fused flash-style attention with the "buggy reshape" addressing:
//   q[b,h,s,d] = QKV[b, h*128 + s/16, (s%16)*192 +   0 + d]
//   k[b,h,s,d] = QKV[b, h*128 + s/16, (s%16)*192 +  64 + d]
//   v[b,h,s,d] = QKV[b, h*128 + s/16, (s%16)*192 + 128 + d]
// Output: ctx[b, s, h*64 + d]
// Grid: (S/64, HEADS, BATCH), 128 threads (ty=0..15 x tx=0..7).
// Each thread: 4 q-rows x (4 score cols per K-tile of 32) ; O microtile 4x8.
// ---------------------------------------------------------------------------
__global__ __launch_bounds__(128) void attn_kernel(
    const float* __restrict__ qkv, float* __restrict__ ctx)
{
    const int h  = blockIdx.y;
    const int b  = blockIdx.z;
    const int q0 = blockIdx.x * 64;
    const float* base = qkv + (size_t)b * SEQ * QKV_N;

    __shared__ float Qs[64][68];   // [q-row][d]
    __shared__ float Kt[64][36];   // [d][k-row] transposed, KT=32
    __shared__ float Vs[32][68];   // [k-row][d]
    __shared__ float Ps[64][36];   // [q-row][k-row] probabilities

    const int tid = threadIdx.x;
    const int ty  = tid >> 3;   // 0..15
    const int tx  = tid & 7;    // 0..7

    // Load Q tile: 64 rows x 64 dims = 1024 float4 / 128 threads = 8 each
#pragma unroll
    for (int it = 0; it < 8; it++) {
        const int i  = tid + it * 128;
        const int r  = i >> 4;
        const int c4 = (i & 15) << 2;
        const int s  = q0 + r;
        const float* p = base + (size_t)(h*128 + (s >> 4)) * QKV_N + (s & 15)*192 + c4;
        *(float4*)&Qs[r][c4] = *(const float4*)p;
    }

    float m_i[4], l_i[4], acc[4][8];
#pragma unroll
    for (int i = 0; i < 4; i++) {
        m_i[i] = -1e30f; l_i[i] = 0.f;
#pragma unroll
        for (int j = 0; j < 8; j++) acc[i][j] = 0.f;
    }
    const float scale = 0.125f;  // 1/sqrt(64)

    for (int j0 = 0; j0 < SEQ; j0 += 32) {
        __syncthreads();   // previous tile's Kt/Vs/Ps consumed
        // Load K (transposed into Kt) and V: 32 rows x 16 float4 = 512 / 128 = 4 each
#pragma unroll
        for (int it = 0; it < 4; it++) {
            const int i  = tid + it * 128;
            const int r  = i >> 4;
            const int c4 = (i & 15) << 2;
            const int s  = j0 + r;
            const float* p = base + (size_t)(h*128 + (s >> 4)) * QKV_N + (s & 15)*192;
            float4 kv = *(const float4*)(p + 64 + c4);
            Kt[c4+0][r] = kv.x; Kt[c4+1][r] = kv.y; Kt[c4+2][r] = kv.z; Kt[c4+3][r] = kv.w;
            *(float4*)&Vs[r][c4] = *(const float4*)(p + 128 + c4);
        }
        __syncthreads();

        // Scores: sc[i][j] = sum_d Q[ty*4+i][d] * K[tx*4+j][d]
        float sc[4][4];
#pragma unroll
        for (int i = 0; i < 4; i++)
#pragma unroll
            for (int j = 0; j < 4; j++) sc[i][j] = 0.f;

#pragma unroll
        for (int d4 = 0; d4 < 64; d4 += 4) {
            float q_r[4][4];
#pragma unroll
            for (int i = 0; i < 4; i++) {
                float4 t = *(float4*)&Qs[ty*4 + i][d4];
                q_r[i][0] = t.x; q_r[i][1] = t.y; q_r[i][2] = t.z; q_r[i][3] = t.w;
            }
#pragma unroll
            for (int dd = 0; dd < 4; dd++) {
                float4 kf = *(float4*)&Kt[d4 + dd][tx*4];
#pragma unroll
                for (int i = 0; i < 4; i++) {
                    sc[i][0] += q_r[i][dd] * kf.x;
                    sc[i][1] += q_r[i][dd] * kf.y;
                    sc[i][2] += q_r[i][dd] * kf.z;
                    sc[i][3] += q_r[i][dd] * kf.w;
                }
            }
        }

        // Online softmax per q-row (row spread across 8 tx lanes)
        float p_r[4][4];
#pragma unroll
        for (int i = 0; i < 4; i++) {
            float rm = -1e30f;
#pragma unroll
            for (int j = 0; j < 4; j++) {
                sc[i][j] *= scale;
                rm = fmaxf(rm, sc[i][j]);
            }
#pragma unroll
            for (int off = 1; off < 8; off <<= 1)
                rm = fmaxf(rm, __shfl_xor_sync(0xffffffffu, rm, off));
            const float newm = fmaxf(m_i[i], rm);
            const float corr = __expf(m_i[i] - newm);
            float rs = 0.f;
#pragma unroll
            for (int j = 0; j < 4; j++) {
                p_r[i][j] = __expf(sc[i][j] - newm);
                rs += p_r[i][j];
            }
#pragma unroll
            for (int off = 1; off < 8; off <<= 1)
                rs += __shfl_xor_sync(0xffffffffu, rs, off);
            l_i[i] = l_i[i] * corr + rs;
            m_i[i] = newm;
#pragma unroll
            for (int j = 0; j < 8; j++) acc[i][j] *= corr;
        }

        // Write P to smem
#pragma unroll
        for (int i = 0; i < 4; i++) {
            float4 pp; pp.x = p_r[i][0]; pp.y = p_r[i][1]; pp.z = p_r[i][2]; pp.w = p_r[i][3];
            *(float4*)&Ps[ty*4 + i][tx*4] = pp;
        }
        __syncthreads();

        // O += P @ V  (O microtile: rows ty*4+i, cols tx*8+j)
#pragma unroll
        for (int jj = 0; jj < 32; jj++) {
            float pv[4];
#pragma unroll
            for (int i = 0; i < 4; i++) pv[i] = Ps[ty*4 + i][jj];
            float4 v0 = *(float4*)&Vs[jj][tx*8];
            float4 v1 = *(float4*)&Vs[jj][tx*8 + 4];
#pragma unroll
            for (int i = 0; i < 4; i++) {
                acc[i][0] += pv[i] * v0.x;
                acc[i][1] += pv[i] * v0.y;
                acc[i][2] += pv[i] * v0.z;
                acc[i][3] += pv[i] * v0.w;
                acc[i][4] += pv[i] * v1.x;
                acc[i][5] += pv[i] * v1.y;
                acc[i][6] += pv[i] * v1.z;
                acc[i][7] += pv[i] * v1.w;
            }
        }
    }

    // Epilogue: ctx[b, s, h*64 + d] = O / l
#pragma unroll
    for (int i = 0; i < 4; i++) {
        const float inv_l = 1.0f / l_i[i];
        const size_t row = (size_t)(b * SEQ + q0 + ty*4 + i);
        const int col = h * HDIM + tx * 8;
        float4 o0, o1;
        o0.x = acc[i][0]*inv_l; o0.y = acc[i][1]*inv_l; o0.z = acc[i][2]*inv_l; o0.w = acc[i][3]*inv_l;
        o1.x = acc[i][4]*inv_l; o1.y = acc[i][5]*inv_l; o1.z = acc[i][6]*inv_l; o1.w = acc[i][7]*inv_l;
        *(float4*)&g_ctx[row * EMB + col]     = o0;
        *(float4*)&g_ctx[row * EMB + col + 4] = o1;
    }
}

// ---------------------------------------------------------------------------
extern "C" void kernel_launch(void* const* d_in, const int* in_sizes, int n_in,
                              void* d_out, int out_size)
{
    const float* x     = (const float*)d_in[0];   // [2, 2048, 1024]
    const float* Wqkv  = (const float*)d_in[1];   // [3072, 1024]
    const float* bqkv  = (const float*)d_in[2];   // [3072]
    const float* Wout  = (const float*)d_in[3];   // [1024, 1024]
    const float* bout  = (const float*)d_in[4];   // [1024]
    float* out = (float*)d_out;                   // [2, 2048, 1024]

    float* qkv_ptr = nullptr;
    float* ctx_ptr = nullptr;
    cudaGetSymbolAddress((void**)&qkv_ptr, g_qkv);
    cudaGetSymbolAddress((void**)&ctx_ptr, g_ctx);

    // 1) QKV projection: [4096, 3072]
    {
        dim3 grid(QKV_N / 128, M_ROWS / 128);
        gemm_nt_kernel<<<grid, 256>>>(x, Wqkv, bqkv, qkv_ptr, M_ROWS, QKV_N, EMB);
    }
    // 2) Fused attention -> ctx [4096, 1024]
    {
        dim3 grid(SEQ / 64, HEADS, BATCH);
        attn_kernel<<<grid, 128>>>(qkv_ptr, ctx_ptr);
    }
    // 3) Output projection: [4096, 1024]
    {
        dim3 grid(EMB / 128, M_ROWS / 128);
        gemm_nt_kernel<<<grid, 256>>>(ctx_ptr, Wout, bout, out, M_ROWS, EMB, EMB);
    }
}

// round 4
// speedup vs baseline: 1.1556x; 1.1556x over previous
#include <cuda_runtime.h>
#include <cuda_bf16.h>
#include <cstdint>

// Problem constants
#define BATCH   2
#define SEQ     2048
#define EMB     1024
#define HEADS   16
#define HDIM    64
#define QKV_N   3072          // 3*EMB
#define M_ROWS  (BATCH*SEQ)   // 4096

// Scratch (allocation-free rule: __device__ globals)
__device__ float g_qkv[(size_t)BATCH * SEQ * QKV_N];   // 48 MB
__device__ float g_ctx[(size_t)BATCH * SEQ * EMB];     // 16 MB

// ---------------------------------------------------------------------------
// fp32 -> tf32 (round to nearest, stored as b32)
// ---------------------------------------------------------------------------
__device__ __forceinline__ uint32_t f2tf32(float f) {
    uint32_t u;
    asm("cvt.rna.tf32.f32 %0, %1;" : "=r"(u) : "f"(f));
    return u;
}

__device__ __forceinline__ void mma_tf32_16x8x8(
    float c[4], uint32_t a0, uint32_t a1, uint32_t a2, uint32_t a3,
    uint32_t b0, uint32_t b1)
{
    asm volatile(
        "mma.sync.aligned.m16n8k8.row.col.f32.tf32.tf32.f32 "
        "{%0,%1,%2,%3}, {%4,%5,%6,%7}, {%8,%9}, {%0,%1,%2,%3};"
        : "+f"(c[0]), "+f"(c[1]), "+f"(c[2]), "+f"(c[3])
        : "r"(a0), "r"(a1), "r"(a2), "r"(a3), "r"(b0), "r"(b1));
}

// ---------------------------------------------------------------------------
// NT GEMM via tf32 tensor cores:
//   C[M,N] = A[M,K] @ B[N,K]^T + bias[N]
// A, B row-major with K contiguous (== mma row.col with B as K-major N rows).
// Block tile 128x128, K-step 32, 8 warps (4m x 2n), warp tile 32x64.
// SMEM holds tf32 bits with k-interleave so A/B fragments are single LDS.64:
//   within each 8-k group, k maps to pos = (k%4)*2 + (k/4)  -> pairs (c, c+4).
// Row stride 40 (uint32) => frag LDS.64 is conflict-free across all 32 banks.
// Requires M%128==0, N%128==0, K%32==0.
// ---------------------------------------------------------------------------
__global__ __launch_bounds__(256, 2) void gemm_tf32_kernel(
    const float* __restrict__ A, const float* __restrict__ B,
    const float* __restrict__ bias, float* __restrict__ C,
    int M, int N, int K)
{
    __shared__ uint32_t As[128][40];
    __shared__ uint32_t Bs[128][40];

    const int tid  = threadIdx.x;
    const int wid  = tid >> 5;
    const int lane = tid & 31;
    const int wm   = wid >> 1;          // 0..3 -> 32 rows each
    const int wn   = wid & 1;           // 0..1 -> 64 cols each
    const int bm   = blockIdx.y * 128;
    const int bn   = blockIdx.x * 128;

    float c[2][8][4];
#pragma unroll
    for (int i = 0; i < 2; i++)
#pragma unroll
        for (int j = 0; j < 8; j++)
#pragma unroll
            for (int e = 0; e < 4; e++) c[i][j][e] = 0.f;

    // gmem loader mapping: 2 threads per row, 16 k-floats each
    const int lrow = tid >> 1;
    const int kb   = (tid & 1) * 16;
    const float* Ap = A + (size_t)(bm + lrow) * K + kb;
    const float* Bp = B + (size_t)(bn + lrow) * K + kb;

    const int frow = lane >> 2;          // 0..7
    const int fc2  = (lane & 3) << 1;    // 0,2,4,6

    for (int k0 = 0; k0 < K; k0 += 32) {
        __syncthreads();
#pragma unroll
        for (int q = 0; q < 4; q++) {
            float4 av = *(const float4*)(Ap + k0 + q * 4);
            float4 bv = *(const float4*)(Bp + k0 + q * 4);
            float va[4] = {av.x, av.y, av.z, av.w};
            float vb[4] = {bv.x, bv.y, bv.z, bv.w};
#pragma unroll
            for (int e = 0; e < 4; e++) {
                const int kk  = kb + q * 4 + e;
                const int pos = (kk >> 3) * 8 + ((kk & 3) << 1) + ((kk >> 2) & 1);
                As[lrow][pos] = f2tf32(va[e]);
                Bs[lrow][pos] = f2tf32(vb[e]);
            }
        }
        __syncthreads();

#pragma unroll
        for (int g = 0; g < 4; g++) {
            const int gp = g * 8 + fc2;
            // A fragments: rows wm*32 + {0,8,16,24} + frow, pairs (c, c+4)
            uint2 a0 = *(uint2*)&As[wm * 32 +  0 + frow][gp];
            uint2 a1 = *(uint2*)&As[wm * 32 +  8 + frow][gp];
            uint2 a2 = *(uint2*)&As[wm * 32 + 16 + frow][gp];
            uint2 a3 = *(uint2*)&As[wm * 32 + 24 + frow][gp];
            // B fragments: 8 n-atoms
            uint2 b[8];
#pragma unroll
            for (int an = 0; an < 8; an++)
                b[an] = *(uint2*)&Bs[wn * 64 + an * 8 + frow][gp];

#pragma unroll
            for (int an = 0; an < 8; an++) {
                mma_tf32_16x8x8(c[0][an], a0.x, a1.x, a0.y, a1.y, b[an].x, b[an].y);
                mma_tf32_16x8x8(c[1][an], a2.x, a3.x, a2.y, a3.y, b[an].x, b[an].y);
            }
        }
    }

    // Epilogue: C fragment rows = base + lane/4 (+8), cols = 2*(lane%4) + {0,1}
    const int crow = bm + wm * 32 + frow;
    const int ccol = bn + wn * 64 + fc2;
#pragma unroll
    for (int am = 0; am < 2; am++) {
        const int r0 = crow + am * 16;
#pragma unroll
        for (int an = 0; an < 8; an++) {
            const int col = ccol + an * 8;
            const float bx = bias[col];
            const float by = bias[col + 1];
            float2 o0, o1;
            o0.x = c[am][an][0] + bx; o0.y = c[am][an][1] + by;
            o1.x = c[am][an][2] + bx; o1.y = c[am][an][3] + by;
            *(float2*)&C[(size_t)r0 * N + col]       = o0;
            *(float2*)&C[(size_t)(r0 + 8) * N + col] = o1;
        }
    }
}

// ---------------------------------------------------------------------------
// Fused flash-style attention with the "buggy reshape" addressing:
//   q[b,h,s,d] = QKV[b, h*128 + s/16, (s%16)*192 +   0 + d]
//   k[b,h,s,d] = QKV[b, h*128 + s/16, (s%16)*192 +  64 + d]
//   v[b,h,s,d] = QKV[b, h*128 + s/16, (s%16)*192 + 128 + d]
// Output: ctx[b, s, h*64 + d]
// Grid: (S/64, HEADS, BATCH), 128 threads (ty=0..15 x tx=0..7).
// ---------------------------------------------------------------------------
__global__ __launch_bounds__(128) void attn_kernel(
    const float* __restrict__ qkv, float* __restrict__ ctx)
{
    const int h  = blockIdx.y;
    const int b  = blockIdx.z;
    const int q0 = blockIdx.x * 64;
    const float* base = qkv + (size_t)b * SEQ * QKV_N;

    __shared__ float Qs[64][68];   // [q-row][d]
    __shared__ float Kt[64][36];   // [d][k-row] transposed, KT=32
    __shared__ float Vs[32][68];   // [k-row][d]
    __shared__ float Ps[64][36];   // [q-row][k-row] probabilities

    const int tid = threadIdx.x;
    const int ty  = tid >> 3;   // 0..15
    const int tx  = tid & 7;    // 0..7

    // Load Q tile: 64 rows x 64 dims = 1024 float4 / 128 threads = 8 each
#pragma unroll
    for (int it = 0; it < 8; it++) {
        const int i  = tid + it * 128;
        const int r  = i >> 4;
        const int c4 = (i & 15) << 2;
        const int s  = q0 + r;
        const float* p = base + (size_t)(h*128 + (s >> 4)) * QKV_N + (s & 15)*192 + c4;
        *(float4*)&Qs[r][c4] = *(const float4*)p;
    }

    float m_i[4], l_i[4], acc[4][8];
#pragma unroll
    for (int i = 0; i < 4; i++) {
        m_i[i] = -1e30f; l_i[i] = 0.f;
#pragma unroll
        for (int j = 0; j < 8; j++) acc[i][j] = 0.f;
    }
    const float scale = 0.125f;  // 1/sqrt(64)

    for (int j0 = 0; j0 < SEQ; j0 += 32) {
        __syncthreads();   // previous tile's Kt/Vs/Ps consumed
#pragma unroll
        for (int it = 0; it < 4; it++) {
            const int i  = tid + it * 128;
            const int r  = i >> 4;
            const int c4 = (i & 15) << 2;
            const int s  = j0 + r;
            const float* p = base + (size_t)(h*128 + (s >> 4)) * QKV_N + (s & 15)*192;
            float4 kv = *(const float4*)(p + 64 + c4);
            Kt[c4+0][r] = kv.x; Kt[c4+1][r] = kv.y; Kt[c4+2][r] = kv.z; Kt[c4+3][r] = kv.w;
            *(float4*)&Vs[r][c4] = *(const float4*)(p + 128 + c4);
        }
        __syncthreads();

        // Scores: sc[i][j] = sum_d Q[ty*4+i][d] * K[tx*4+j][d]
        float sc[4][4];
#pragma unroll
        for (int i = 0; i < 4; i++)
#pragma unroll
            for (int j = 0; j < 4; j++) sc[i][j] = 0.f;

#pragma unroll
        for (int d4 = 0; d4 < 64; d4 += 4) {
            float q_r[4][4];
#pragma unroll
            for (int i = 0; i < 4; i++) {
                float4 t = *(float4*)&Qs[ty*4 + i][d4];
                q_r[i][0] = t.x; q_r[i][1] = t.y; q_r[i][2] = t.z; q_r[i][3] = t.w;
            }
#pragma unroll
            for (int dd = 0; dd < 4; dd++) {
                float4 kf = *(float4*)&Kt[d4 + dd][tx*4];
#pragma unroll
                for (int i = 0; i < 4; i++) {
                    sc[i][0] += q_r[i][dd] * kf.x;
                    sc[i][1] += q_r[i][dd] * kf.y;
                    sc[i][2] += q_r[i][dd] * kf.z;
                    sc[i][3] += q_r[i][dd] * kf.w;
                }
            }
        }

        // Online softmax per q-row (row spread across 8 tx lanes)
        float p_r[4][4];
#pragma unroll
        for (int i = 0; i < 4; i++) {
            float rm = -1e30f;
#pragma unroll
            for (int j = 0; j < 4; j++) {
                sc[i][j] *= scale;
                rm = fmaxf(rm, sc[i][j]);
            }
#pragma unroll
            for (int off = 1; off < 8; off <<= 1)
                rm = fmaxf(rm, __shfl_xor_sync(0xffffffffu, rm, off));
            const float newm = fmaxf(m_i[i], rm);
            const float corr = __expf(m_i[i] - newm);
            float rs = 0.f;
#pragma unroll
            for (int j = 0; j < 4; j++) {
                p_r[i][j] = __expf(sc[i][j] - newm);
                rs += p_r[i][j];
            }
#pragma unroll
            for (int off = 1; off < 8; off <<= 1)
                rs += __shfl_xor_sync(0xffffffffu, rs, off);
            l_i[i] = l_i[i] * corr + rs;
            m_i[i] = newm;
#pragma unroll
            for (int j = 0; j < 8; j++) acc[i][j] *= corr;
        }

        // Write P to smem
#pragma unroll
        for (int i = 0; i < 4; i++) {
            float4 pp; pp.x = p_r[i][0]; pp.y = p_r[i][1]; pp.z = p_r[i][2]; pp.w = p_r[i][3];
            *(float4*)&Ps[ty*4 + i][tx*4] = pp;
        }
        __syncthreads();

        // O += P @ V  (O microtile: rows ty*4+i, cols tx*8+j)
#pragma unroll
        for (int jj = 0; jj < 32; jj++) {
            float pv[4];
#pragma unroll
            for (int i = 0; i < 4; i++) pv[i] = Ps[ty*4 + i][jj];
            float4 v0 = *(float4*)&Vs[jj][tx*8];
            float4 v1 = *(float4*)&Vs[jj][tx*8 + 4];
#pragma unroll
            for (int i = 0; i < 4; i++) {
                acc[i][0] += pv[i] * v0.x;
                acc[i][1] += pv[i] * v0.y;
                acc[i][2] += pv[i] * v0.z;
                acc[i][3] += pv[i] * v0.w;
                acc[i][4] += pv[i] * v1.x;
                acc[i][5] += pv[i] * v1.y;
                acc[i][6] += pv[i] * v1.z;
                acc[i][7] += pv[i] * v1.w;
            }
        }
    }

    // Epilogue: ctx[b, s, h*64 + d] = O / l
#pragma unroll
    for (int i = 0; i < 4; i++) {
        const float inv_l = 1.0f / l_i[i];
        const size_t row = (size_t)(b * SEQ + q0 + ty*4 + i);
        const int col = h * HDIM + tx * 8;
        float4 o0, o1;
        o0.x = acc[i][0]*inv_l; o0.y = acc[i][1]*inv_l; o0.z = acc[i][2]*inv_l; o0.w = acc[i][3]*inv_l;
        o1.x = acc[i][4]*inv_l; o1.y = acc[i][5]*inv_l; o1.z = acc[i][6]*inv_l; o1.w = acc[i][7]*inv_l;
        *(float4*)&g_ctx[row * EMB + col]     = o0;
        *(float4*)&g_ctx[row * EMB + col + 4] = o1;
    }
}

// ---------------------------------------------------------------------------
extern "C" void kernel_launch(void* const* d_in, const int* in_sizes, int n_in,
                              void* d_out, int out_size)
{
    const float* x     = (const float*)d_in[0];   // [2, 2048, 1024]
    const float* Wqkv  = (const float*)d_in[1];   // [3072, 1024]
    const float* bqkv  = (const float*)d_in[2];   // [3072]
    const float* Wout  = (const float*)d_in[3];   // [1024, 1024]
    const float* bout  = (const float*)d_in[4];   // [1024]
    float* out = (float*)d_out;                   // [2, 2048, 1024]

    float* qkv_ptr = nullptr;
    float* ctx_ptr = nullptr;
    cudaGetSymbolAddress((void**)&qkv_ptr, g_qkv);
    cudaGetSymbolAddress((void**)&ctx_ptr, g_ctx);

    // 1) QKV projection: [4096, 3072] via tf32 tensor cores
    {
        dim3 grid(QKV_N / 128, M_ROWS / 128);
        gemm_tf32_kernel<<<grid, 256>>>(x, Wqkv, bqkv, qkv_ptr, M_ROWS, QKV_N, EMB);
    }
    // 2) Fused attention -> ctx [4096, 1024]
    {
        dim3 grid(SEQ / 64, HEADS, BATCH);
        attn_kernel<<<grid, 128>>>(qkv_ptr, ctx_ptr);
    }
    // 3) Output projection: [4096, 1024] via tf32 tensor cores
    {
        dim3 grid(EMB / 128, M_ROWS / 128);
        gemm_tf32_kernel<<<grid, 256>>>(ctx_ptr, Wout, bout, out, M_ROWS, EMB, EMB);
    }
}